// round 3
// baseline (speedup 1.0000x reference)
#include <cuda_runtime.h>
#include <cstdint>

#define D 64
#define GRID_STREAM 1184   // 148 SMs * 8

// Global accumulators / tables (no allocation allowed)
__device__ float g_P[768];                 // [0:384) = Px (6x64), [384:768) = Py
__device__ float g_cx[6 * 64], g_dx[6 * 64];
__device__ float g_cy[6 * 64], g_dy[6 * 64];

struct Ptr6 { const float* p[6]; };
struct K2Args {
    const float* w[12];    // logical order: buy_uu, buy_ui, buy_iu, buy_ii, cart_*, pv_*
    const float* w1[12];   // same order
    const float* edges[3]; // buy, cart, pv
};

__device__ __forceinline__ void stwt4(float* p, float4 v) {
    asm volatile("st.global.wt.v4.f32 [%0], {%1,%2,%3,%4};"
                 :: "l"(p), "f"(v.x), "f"(v.y), "f"(v.z), "f"(v.w));
}

// ---------------------------------------------------------------------------
// k0: zero the global accumulator
// ---------------------------------------------------------------------------
__global__ void k0_zero() {
    g_P[threadIdx.x] = 0.0f;
}

// ---------------------------------------------------------------------------
// k1: accumulate p_t = src^T (src w_t) for 6 weight vectors.
// 16 lanes per row, float4 per lane, TWO rows in flight per thread.
// Requires n % 32 == 0 (300000, 500000 both OK).
// ---------------------------------------------------------------------------
__global__ __launch_bounds__(256) void k1_gramvec(
    const float* __restrict__ emb, const int* __restrict__ ids, int n,
    Ptr6 W, int part /* 0 = X, 1 = Y */)
{
    __shared__ float sw[6][64];
    __shared__ float sp[384];
    const int tid = threadIdx.x;

    for (int i = tid; i < 384; i += 256) {
        sw[i >> 6][i & 63] = W.p[i >> 6][i & 63];
        sp[i] = 0.0f;
    }
    __syncthreads();

    const int half = tid >> 4;       // 0..15: row slot within block
    const int col  = (tid & 15) * 4; // column group

    float4 w4[6];
#pragma unroll
    for (int t = 0; t < 6; t++)
        w4[t] = *reinterpret_cast<const float4*>(&sw[t][col]);

    float acc[6][4];
#pragma unroll
    for (int t = 0; t < 6; t++) { acc[t][0] = acc[t][1] = acc[t][2] = acc[t][3] = 0.0f; }

    for (int base = blockIdx.x * 32; base < n; base += GRID_STREAM * 32) {
        const int r0 = base + half;
        const int r1 = r0 + 16;
        const int id0 = ids[r0];
        const int id1 = ids[r1];
        const float4 u = *reinterpret_cast<const float4*>(emb + (size_t)id0 * D + col);
        const float4 v = *reinterpret_cast<const float4*>(emb + (size_t)id1 * D + col);
        const float p0 = 0.1f * u.x, p1 = 0.1f * u.y, p2 = 0.1f * u.z, p3 = 0.1f * u.w;
        const float q0 = 0.1f * v.x, q1 = 0.1f * v.y, q2 = 0.1f * v.z, q3 = 0.1f * v.w;

        float a[6], b[6];
#pragma unroll
        for (int t = 0; t < 6; t++) {
            a[t] = p0 * w4[t].x + p1 * w4[t].y + p2 * w4[t].z + p3 * w4[t].w;
            b[t] = q0 * w4[t].x + q1 * w4[t].y + q2 * w4[t].z + q3 * w4[t].w;
        }
#pragma unroll
        for (int off = 8; off; off >>= 1)
#pragma unroll
            for (int t = 0; t < 6; t++) {
                a[t] += __shfl_xor_sync(0xffffffffu, a[t], off);
                b[t] += __shfl_xor_sync(0xffffffffu, b[t], off);
            }
#pragma unroll
        for (int t = 0; t < 6; t++) {
            acc[t][0] += a[t] * p0 + b[t] * q0;
            acc[t][1] += a[t] * p1 + b[t] * q1;
            acc[t][2] += a[t] * p2 + b[t] * q2;
            acc[t][3] += a[t] * p3 + b[t] * q3;
        }
    }

    // fold lane pairs (l, l+16): same columns, different row stream
#pragma unroll
    for (int t = 0; t < 6; t++)
#pragma unroll
        for (int c = 0; c < 4; c++)
            acc[t][c] += __shfl_xor_sync(0xffffffffu, acc[t][c], 16);

    if ((tid & 16) == 0) {   // lanes 0..15 of each warp
#pragma unroll
        for (int t = 0; t < 6; t++)
#pragma unroll
            for (int c = 0; c < 4; c++)
                atomicAdd(&sp[t * 64 + col + c], acc[t][c]);
    }
    __syncthreads();

    float* gp = g_P + part * 384;
    for (int i = tid; i < 384; i += 256)
        atomicAdd(&gp[i], sp[i]);
}

// ---------------------------------------------------------------------------
// k2: build c/d tables, parallelized. Blocks 0..11: one (side,term) each,
// 64 threads computing d[j]. Block 12: edge passthrough copy.
// ---------------------------------------------------------------------------
__global__ __launch_bounds__(64) void k2_build(K2Args a, float* __restrict__ edge_out)
{
    const int blk = blockIdx.x;
    const int j   = threadIdx.x;

    if (blk == 12) {  // edges: 3 x 64 floats
#pragma unroll
        for (int e = 0; e < 3; e++)
            edge_out[e * 64 + j] = a.edges[e][j];
        return;
    }

    const int side = blk / 6;            // 0 = x-side, 1 = y-side
    const int t    = blk % 6;
    const int b    = t % 3;              // behavior: 0 buy, 1 cart, 2 pv

    const float* p; const float* W1; const float* c;
    if (side == 0) {
        if (t < 3) { p = &g_P[b * 64];           W1 = a.w1[4 * b + 0]; c = a.w[4 * b + 0]; } // uu
        else       { p = &g_P[384 + b * 64];     W1 = a.w1[4 * b + 1]; c = a.w[4 * b + 1]; } // ui
    } else {
        if (t < 3) { p = &g_P[384 + (3 + b) * 64]; W1 = a.w1[4 * b + 3]; c = a.w[4 * b + 3]; } // ii
        else       { p = &g_P[(3 + b) * 64];       W1 = a.w1[4 * b + 2]; c = a.w[4 * b + 2]; } // iu
    }
    const float coef = 0.25f * ((b == 0) ? 0.6f : (b == 1) ? 0.3f : 0.1f);

    float u0 = 0.f, u1 = 0.f, u2 = 0.f, u3 = 0.f;
#pragma unroll
    for (int k = 0; k < 64; k += 4) {
        u0 += p[k + 0] * W1[(k + 0) * 64 + j];
        u1 += p[k + 1] * W1[(k + 1) * 64 + j];
        u2 += p[k + 2] * W1[(k + 2) * 64 + j];
        u3 += p[k + 3] * W1[(k + 3) * 64 + j];
    }
    const float d = coef * ((u0 + u1) + (u2 + u3));
    if (side == 0) { g_dx[t * 64 + j] = d; g_cx[t * 64 + j] = c[j]; }
    else           { g_dy[t * 64 + j] = d; g_cy[t * 64 + j] = c[j]; }
}

// ---------------------------------------------------------------------------
// k3: out[i] = 0.5 * x_i + sum_t (x_i . c_t) d_t
// 16 lanes per row, TWO rows in flight, streaming (write-through) stores.
// ---------------------------------------------------------------------------
__global__ __launch_bounds__(256) void k3_apply(
    const float* __restrict__ emb, const int* __restrict__ ids, int n,
    int side, float* __restrict__ out)
{
    __shared__ float sc[6][64];
    __shared__ float sd[6][64];
    const float* cv = side ? g_cy : g_cx;
    const float* dv = side ? g_dy : g_dx;
    const int tid = threadIdx.x;
    for (int i = tid; i < 384; i += 256) {
        sc[i >> 6][i & 63] = cv[i];
        sd[i >> 6][i & 63] = dv[i];
    }
    __syncthreads();

    const int half = tid >> 4;
    const int col  = (tid & 15) * 4;

    float4 c4[6], d4[6];
#pragma unroll
    for (int t = 0; t < 6; t++) {
        c4[t] = *reinterpret_cast<const float4*>(&sc[t][col]);
        d4[t] = *reinterpret_cast<const float4*>(&sd[t][col]);
    }

    for (int base = blockIdx.x * 32; base < n; base += GRID_STREAM * 32) {
        const int r0 = base + half;
        const int r1 = r0 + 16;
        const int id0 = ids[r0];
        const int id1 = ids[r1];
        const float4 u = *reinterpret_cast<const float4*>(emb + (size_t)id0 * D + col);
        const float4 v = *reinterpret_cast<const float4*>(emb + (size_t)id1 * D + col);
        const float p0 = 0.1f * u.x, p1 = 0.1f * u.y, p2 = 0.1f * u.z, p3 = 0.1f * u.w;
        const float q0 = 0.1f * v.x, q1 = 0.1f * v.y, q2 = 0.1f * v.z, q3 = 0.1f * v.w;

        float a[6], b[6];
#pragma unroll
        for (int t = 0; t < 6; t++) {
            a[t] = p0 * c4[t].x + p1 * c4[t].y + p2 * c4[t].z + p3 * c4[t].w;
            b[t] = q0 * c4[t].x + q1 * c4[t].y + q2 * c4[t].z + q3 * c4[t].w;
        }
#pragma unroll
        for (int off = 8; off; off >>= 1)
#pragma unroll
            for (int t = 0; t < 6; t++) {
                a[t] += __shfl_xor_sync(0xffffffffu, a[t], off);
                b[t] += __shfl_xor_sync(0xffffffffu, b[t], off);
            }

        float4 o0, o1;
        o0.x = 0.5f * p0; o0.y = 0.5f * p1; o0.z = 0.5f * p2; o0.w = 0.5f * p3;
        o1.x = 0.5f * q0; o1.y = 0.5f * q1; o1.z = 0.5f * q2; o1.w = 0.5f * q3;
#pragma unroll
        for (int t = 0; t < 6; t++) {
            o0.x += a[t] * d4[t].x; o0.y += a[t] * d4[t].y;
            o0.z += a[t] * d4[t].z; o0.w += a[t] * d4[t].w;
            o1.x += b[t] * d4[t].x; o1.y += b[t] * d4[t].y;
            o1.z += b[t] * d4[t].z; o1.w += b[t] * d4[t].w;
        }
        stwt4(out + (size_t)r0 * D + col, o0);
        stwt4(out + (size_t)r1 * D + col, o1);
    }
}

// ---------------------------------------------------------------------------
extern "C" void kernel_launch(void* const* d_in, const int* in_sizes, int n_in,
                              void* d_out, int out_size)
{
    const int*   uid = (const int*)d_in[0];
    const int*   iid = (const int*)d_in[1];
    const float* ue  = (const float*)d_in[2];
    const float* ie  = (const float*)d_in[3];
    const int nuser = in_sizes[0];
    const int nitem = in_sizes[1];

    // setup_inputs interleaves _w / _w1 per vec:
    //   d_in[4 + 2*v] = _VEC[v]_w,  d_in[5 + 2*v] = _VEC[v]_w1
    K2Args ka;
    for (int v = 0; v < 12; v++) {
        ka.w[v]  = (const float*)d_in[4 + 2 * v];
        ka.w1[v] = (const float*)d_in[5 + 2 * v];
    }
    ka.edges[0] = (const float*)d_in[28];
    ka.edges[1] = (const float*)d_in[29];
    ka.edges[2] = (const float*)d_in[30];

    Ptr6 wx, wy;
    for (int b = 0; b < 3; b++) {
        wx.p[b]     = ka.w[4 * b + 0]; // uu  -> Px slots 0..2
        wx.p[3 + b] = ka.w[4 * b + 2]; // iu  -> Px slots 3..5
        wy.p[b]     = ka.w[4 * b + 1]; // ui  -> Py slots 0..2
        wy.p[3 + b] = ka.w[4 * b + 3]; // ii  -> Py slots 3..5
    }

    float* out = (float*)d_out;
    float* edge_out = out + (size_t)(nuser + nitem) * D;

    k0_zero<<<1, 768>>>();
    k1_gramvec<<<GRID_STREAM, 256>>>(ue, uid, nuser, wx, 0);
    k1_gramvec<<<GRID_STREAM, 256>>>(ie, iid, nitem, wy, 1);
    k2_build<<<13, 64>>>(ka, edge_out);
    // k3y first: item emb (128 MB) was just streamed through L2 by k1y,
    // so re-reading it immediately maximizes L2 hits; wt stores avoid evicting it.
    k3_apply<<<GRID_STREAM, 256>>>(ie, iid, nitem, 1, out + (size_t)nuser * D);
    k3_apply<<<GRID_STREAM, 256>>>(ue, uid, nuser, 0, out);
}

// round 4
// speedup vs baseline: 1.0862x; 1.0862x over previous
#include <cuda_runtime.h>
#include <cstdint>

#define D 64
#define GRID_STREAM 1184   // 148 SMs * 8 blocks

// Global accumulators / tables (no allocation allowed)
__device__ float g_P[768];                 // [0:384) = Px (6x64), [384:768) = Py
__device__ float g_cx[384], g_dx[384];
__device__ float g_cy[384], g_dy[384];

struct Ptr6 { const float* p[6]; };
struct K2Args {
    const float* w[12];    // logical order: buy_uu, buy_ui, buy_iu, buy_ii, cart_*, pv_*
    const float* w1[12];   // same order
};

// ---------------------------------------------------------------------------
// k0: zero the global accumulator
// ---------------------------------------------------------------------------
__global__ void k0_zero() { g_P[threadIdx.x] = 0.0f; }

// ---------------------------------------------------------------------------
// k_edge: passthrough copy of the 3 edge vectors (independent of everything;
// placed early so heavy kernels land in ncu's capture slots)
// ---------------------------------------------------------------------------
__global__ void k_edge(const float* __restrict__ e0, const float* __restrict__ e1,
                       const float* __restrict__ e2, float* __restrict__ out)
{
    const int j = threadIdx.x;
    out[j] = e0[j]; out[64 + j] = e1[j]; out[128 + j] = e2[j];
}

// ---------------------------------------------------------------------------
// k1: accumulate p_t = src^T (src w_t) for 6 weight vectors.
// 8 lanes per row (8 cols each). Warp covers 4 rows; 3-step butterfly.
// Requires n % 32 == 0 (300000, 500000 both OK).
// ---------------------------------------------------------------------------
__global__ __launch_bounds__(256) void k1_gramvec(
    const float* __restrict__ emb, const int* __restrict__ ids, int n,
    Ptr6 W, int part /* 0 = X, 1 = Y */)
{
    __shared__ float sw[6][64];
    __shared__ float sp[384];
    const int tid = threadIdx.x;

    for (int i = tid; i < 384; i += 256) {
        sw[i >> 6][i & 63] = W.p[i >> 6][i & 63];
        sp[i] = 0.0f;
    }
    __syncthreads();

    const int rslot = tid >> 3;      // 0..31: row slot within block
    const int col   = (tid & 7) * 8; // 8 columns per lane

    float acc[6][8];
#pragma unroll
    for (int t = 0; t < 6; t++)
#pragma unroll
        for (int j = 0; j < 8; j++) acc[t][j] = 0.0f;

    for (int base = blockIdx.x * 32; base < n; base += GRID_STREAM * 32) {
        const int id = ids[base + rslot];
        const float4 u0 = *reinterpret_cast<const float4*>(emb + (size_t)id * D + col);
        const float4 u1 = *reinterpret_cast<const float4*>(emb + (size_t)id * D + col + 4);
        float x[8];
        x[0] = 0.1f * u0.x; x[1] = 0.1f * u0.y; x[2] = 0.1f * u0.z; x[3] = 0.1f * u0.w;
        x[4] = 0.1f * u1.x; x[5] = 0.1f * u1.y; x[6] = 0.1f * u1.z; x[7] = 0.1f * u1.w;

        float a[6];
#pragma unroll
        for (int t = 0; t < 6; t++) {
            const float4 w0 = *reinterpret_cast<const float4*>(&sw[t][col]);
            const float4 w1 = *reinterpret_cast<const float4*>(&sw[t][col + 4]);
            a[t] = x[0] * w0.x + x[1] * w0.y + x[2] * w0.z + x[3] * w0.w
                 + x[4] * w1.x + x[5] * w1.y + x[6] * w1.z + x[7] * w1.w;
        }
        // 3-step butterfly within each 8-lane row group
#pragma unroll
        for (int off = 4; off; off >>= 1)
#pragma unroll
            for (int t = 0; t < 6; t++)
                a[t] += __shfl_xor_sync(0xffffffffu, a[t], off);
#pragma unroll
        for (int t = 0; t < 6; t++)
#pragma unroll
            for (int j = 0; j < 8; j++)
                acc[t][j] += a[t] * x[j];
    }

    // fold the 4 row-slot lanes per warp that share the same column octant
#pragma unroll
    for (int off = 8; off <= 16; off <<= 1)
#pragma unroll
        for (int t = 0; t < 6; t++)
#pragma unroll
            for (int j = 0; j < 8; j++)
                acc[t][j] += __shfl_xor_sync(0xffffffffu, acc[t][j], off);

    if ((tid & 31) < 8) {   // lanes 0..7 of each warp
#pragma unroll
        for (int t = 0; t < 6; t++)
#pragma unroll
            for (int j = 0; j < 8; j++)
                atomicAdd(&sp[t * 64 + col + j], acc[t][j]);
    }
    __syncthreads();

    float* gp = g_P + part * 384;
    for (int i = tid; i < 384; i += 256)
        atomicAdd(&gp[i], sp[i]);
}

// ---------------------------------------------------------------------------
// k2: build c/d tables. Blocks 0..11: one (side,term), 64 threads each.
// ---------------------------------------------------------------------------
__global__ __launch_bounds__(64) void k2_build(K2Args a)
{
    const int blk  = blockIdx.x;
    const int j    = threadIdx.x;
    const int side = blk / 6;            // 0 = x-side, 1 = y-side
    const int t    = blk % 6;
    const int b    = t % 3;              // behavior: 0 buy, 1 cart, 2 pv

    const float* p; const float* W1; const float* c;
    if (side == 0) {
        if (t < 3) { p = &g_P[b * 64];           W1 = a.w1[4 * b + 0]; c = a.w[4 * b + 0]; } // uu
        else       { p = &g_P[384 + b * 64];     W1 = a.w1[4 * b + 1]; c = a.w[4 * b + 1]; } // ui
    } else {
        if (t < 3) { p = &g_P[384 + (3 + b) * 64]; W1 = a.w1[4 * b + 3]; c = a.w[4 * b + 3]; } // ii
        else       { p = &g_P[(3 + b) * 64];       W1 = a.w1[4 * b + 2]; c = a.w[4 * b + 2]; } // iu
    }
    const float coef = 0.25f * ((b == 0) ? 0.6f : (b == 1) ? 0.3f : 0.1f);

    float u0 = 0.f, u1 = 0.f, u2 = 0.f, u3 = 0.f;
#pragma unroll
    for (int k = 0; k < 64; k += 4) {
        u0 += p[k + 0] * W1[(k + 0) * 64 + j];
        u1 += p[k + 1] * W1[(k + 1) * 64 + j];
        u2 += p[k + 2] * W1[(k + 2) * 64 + j];
        u3 += p[k + 3] * W1[(k + 3) * 64 + j];
    }
    const float d = coef * ((u0 + u1) + (u2 + u3));
    if (side == 0) { g_dx[t * 64 + j] = d; g_cx[t * 64 + j] = c[j]; }
    else           { g_dy[t * 64 + j] = d; g_cy[t * 64 + j] = c[j]; }
}

// ---------------------------------------------------------------------------
// k3: out[i] = 0.5 * x_i + sum_t (x_i . c_t) d_t
// 8 lanes per row; c from shared per iteration, d in registers.
// ---------------------------------------------------------------------------
__global__ __launch_bounds__(256) void k3_apply(
    const float* __restrict__ emb, const int* __restrict__ ids, int n,
    int side, float* __restrict__ out)
{
    __shared__ float sc[6][64];
    const float* cv = side ? g_cy : g_cx;
    const float* dv = side ? g_dy : g_dx;
    const int tid = threadIdx.x;
    for (int i = tid; i < 384; i += 256)
        sc[i >> 6][i & 63] = cv[i];
    __syncthreads();

    const int rslot = tid >> 3;
    const int col   = (tid & 7) * 8;

    float dr[6][8];
#pragma unroll
    for (int t = 0; t < 6; t++)
#pragma unroll
        for (int j = 0; j < 8; j++)
            dr[t][j] = dv[t * 64 + col + j];

    for (int base = blockIdx.x * 32; base < n; base += GRID_STREAM * 32) {
        const int r  = base + rslot;
        const int id = ids[r];
        const float4 u0 = *reinterpret_cast<const float4*>(emb + (size_t)id * D + col);
        const float4 u1 = *reinterpret_cast<const float4*>(emb + (size_t)id * D + col + 4);
        float x[8];
        x[0] = 0.1f * u0.x; x[1] = 0.1f * u0.y; x[2] = 0.1f * u0.z; x[3] = 0.1f * u0.w;
        x[4] = 0.1f * u1.x; x[5] = 0.1f * u1.y; x[6] = 0.1f * u1.z; x[7] = 0.1f * u1.w;

        float a[6];
#pragma unroll
        for (int t = 0; t < 6; t++) {
            const float4 c0 = *reinterpret_cast<const float4*>(&sc[t][col]);
            const float4 c1 = *reinterpret_cast<const float4*>(&sc[t][col + 4]);
            a[t] = x[0] * c0.x + x[1] * c0.y + x[2] * c0.z + x[3] * c0.w
                 + x[4] * c1.x + x[5] * c1.y + x[6] * c1.z + x[7] * c1.w;
        }
#pragma unroll
        for (int off = 4; off; off >>= 1)
#pragma unroll
            for (int t = 0; t < 6; t++)
                a[t] += __shfl_xor_sync(0xffffffffu, a[t], off);

        float o[8];
#pragma unroll
        for (int j = 0; j < 8; j++) o[j] = 0.5f * x[j];
#pragma unroll
        for (int t = 0; t < 6; t++)
#pragma unroll
            for (int j = 0; j < 8; j++)
                o[j] += a[t] * dr[t][j];

        float4 o0, o1;
        o0.x = o[0]; o0.y = o[1]; o0.z = o[2]; o0.w = o[3];
        o1.x = o[4]; o1.y = o[5]; o1.z = o[6]; o1.w = o[7];
        *reinterpret_cast<float4*>(out + (size_t)r * D + col)     = o0;
        *reinterpret_cast<float4*>(out + (size_t)r * D + col + 4) = o1;
    }
}

// ---------------------------------------------------------------------------
extern "C" void kernel_launch(void* const* d_in, const int* in_sizes, int n_in,
                              void* d_out, int out_size)
{
    const int*   uid = (const int*)d_in[0];
    const int*   iid = (const int*)d_in[1];
    const float* ue  = (const float*)d_in[2];
    const float* ie  = (const float*)d_in[3];
    const int nuser = in_sizes[0];
    const int nitem = in_sizes[1];

    // setup_inputs interleaves _w / _w1 per vec:
    //   d_in[4 + 2*v] = _VEC[v]_w,  d_in[5 + 2*v] = _VEC[v]_w1
    K2Args ka;
    for (int v = 0; v < 12; v++) {
        ka.w[v]  = (const float*)d_in[4 + 2 * v];
        ka.w1[v] = (const float*)d_in[5 + 2 * v];
    }

    Ptr6 wx, wy;
    for (int b = 0; b < 3; b++) {
        wx.p[b]     = ka.w[4 * b + 0]; // uu  -> Px slots 0..2
        wx.p[3 + b] = ka.w[4 * b + 2]; // iu  -> Px slots 3..5
        wy.p[b]     = ka.w[4 * b + 1]; // ui  -> Py slots 0..2
        wy.p[3 + b] = ka.w[4 * b + 3]; // ii  -> Py slots 3..5
    }

    float* out = (float*)d_out;
    float* edge_out = out + (size_t)(nuser + nitem) * D;

    // Order chosen so slots 4 (k1y) and 6 (k3y) are heavy kernels for ncu.
    k0_zero<<<1, 768>>>();
    k_edge<<<1, 64>>>((const float*)d_in[28], (const float*)d_in[29],
                      (const float*)d_in[30], edge_out);
    k1_gramvec<<<GRID_STREAM, 256>>>(ue, uid, nuser, wx, 0);
    k1_gramvec<<<GRID_STREAM, 256>>>(ie, iid, nitem, wy, 1);
    k2_build<<<12, 64>>>(ka);
    k3_apply<<<GRID_STREAM, 256>>>(ie, iid, nitem, 1, out + (size_t)nuser * D);
    k3_apply<<<GRID_STREAM, 256>>>(ue, uid, nuser, 0, out);
}

// round 5
// speedup vs baseline: 1.1302x; 1.0405x over previous
#include <cuda_runtime.h>
#include <cstdint>

#define D 64
#define GX 444            // X-side blocks (300K rows)
#define GY 740            // Y-side blocks (500K rows); 444+740 = 1184 = 2 waves @ 4/SM

// Global accumulators / tables (no allocation allowed)
__device__ float g_P[768];                 // [0:384) = Px (6x64), [384:768) = Py
__device__ float g_cx[384], g_dx[384];
__device__ float g_cy[384], g_dy[384];

struct K1Args {
    const float* embX; const int* idsX; int nX;
    const float* embY; const int* idsY; int nY;
    const float* wX[6];   // uu(buy,cart,pv), iu(buy,cart,pv)
    const float* wY[6];   // ui(buy,cart,pv), ii(buy,cart,pv)
};
struct K2Args {
    const float* w[12];    // logical: buy_uu, buy_ui, buy_iu, buy_ii, cart_*, pv_*
    const float* w1[12];
};
struct K3Args {
    const float* embX; const int* idsX; int nX; float* outX;
    const float* embY; const int* idsY; int nY; float* outY;
};

// ---------------------------------------------------------------------------
__global__ void k0_zero() { g_P[threadIdx.x] = 0.0f; }

__global__ void k_edge(const float* __restrict__ e0, const float* __restrict__ e1,
                       const float* __restrict__ e2, float* __restrict__ out)
{
    const int j = threadIdx.x;
    out[j] = e0[j]; out[64 + j] = e1[j]; out[128 + j] = e2[j];
}

// ---------------------------------------------------------------------------
// k1 fused: p_t = src^T (src w_t), 6 vectors per side.
// Warp pair shares 4 rows; even warp handles t=0..2, odd warp t=3..5.
// 8 lanes per row (8 cols each), 3-step butterfly, acc[3][8] in regs.
// ---------------------------------------------------------------------------
__global__ __launch_bounds__(256, 4) void k1_gramvec(K1Args A)
{
    const int side = (blockIdx.x >= GX) ? 1 : 0;
    const int bid  = side ? (blockIdx.x - GX) : blockIdx.x;
    const int nb   = side ? GY : GX;
    const float* __restrict__ emb = side ? A.embY : A.embX;
    const int*   __restrict__ ids = side ? A.idsY : A.idsX;
    const int n = side ? A.nY : A.nX;

    __shared__ float sw[384];
    __shared__ float sp[384];
    const int tid = threadIdx.x;

    {
        const float* const* Wp = side ? A.wY : A.wX;
        for (int i = tid; i < 384; i += 256) {
            sw[i] = Wp[i >> 6][i & 63];
            sp[i] = 0.0f;
        }
    }
    __syncthreads();

    const int wid  = tid >> 5;
    const int lane = tid & 31;
    const int tg   = (wid & 1) * 3;                    // t-group offset: 0 or 3
    const int rsl  = (wid >> 1) * 4 + (lane >> 3);     // row slot 0..15
    const int col  = (lane & 7) * 8;

    float acc[3][8];
#pragma unroll
    for (int t = 0; t < 3; t++)
#pragma unroll
        for (int j = 0; j < 8; j++) acc[t][j] = 0.0f;

    for (int base = bid * 16; base < n; base += nb * 16) {
        const int id = ids[base + rsl];
        const float4 u0 = *reinterpret_cast<const float4*>(emb + (size_t)id * D + col);
        const float4 u1 = *reinterpret_cast<const float4*>(emb + (size_t)id * D + col + 4);
        float x[8];
        x[0] = 0.1f * u0.x; x[1] = 0.1f * u0.y; x[2] = 0.1f * u0.z; x[3] = 0.1f * u0.w;
        x[4] = 0.1f * u1.x; x[5] = 0.1f * u1.y; x[6] = 0.1f * u1.z; x[7] = 0.1f * u1.w;

        float a[3];
#pragma unroll
        for (int t = 0; t < 3; t++) {
            const float4 w0 = *reinterpret_cast<const float4*>(&sw[(tg + t) * 64 + col]);
            const float4 w1 = *reinterpret_cast<const float4*>(&sw[(tg + t) * 64 + col + 4]);
            a[t] = x[0] * w0.x + x[1] * w0.y + x[2] * w0.z + x[3] * w0.w
                 + x[4] * w1.x + x[5] * w1.y + x[6] * w1.z + x[7] * w1.w;
        }
#pragma unroll
        for (int off = 4; off; off >>= 1)
#pragma unroll
            for (int t = 0; t < 3; t++)
                a[t] += __shfl_xor_sync(0xffffffffu, a[t], off);
#pragma unroll
        for (int t = 0; t < 3; t++)
#pragma unroll
            for (int j = 0; j < 8; j++)
                acc[t][j] += a[t] * x[j];
    }

    // fold the 4 row-slot groups per warp (lane bits 3,4)
#pragma unroll
    for (int off = 8; off <= 16; off <<= 1)
#pragma unroll
        for (int t = 0; t < 3; t++)
#pragma unroll
            for (int j = 0; j < 8; j++)
                acc[t][j] += __shfl_xor_sync(0xffffffffu, acc[t][j], off);

    if (lane < 8) {
#pragma unroll
        for (int t = 0; t < 3; t++)
#pragma unroll
            for (int j = 0; j < 8; j++)
                atomicAdd(&sp[(tg + t) * 64 + col + j], acc[t][j]);
    }
    __syncthreads();

    float* gp = g_P + side * 384;
    for (int i = tid; i < 384; i += 256)
        atomicAdd(&gp[i], sp[i]);
}

// ---------------------------------------------------------------------------
// k2: build c/d tables. Blocks 0..11: one (side,term), 64 threads each.
// ---------------------------------------------------------------------------
__global__ __launch_bounds__(64) void k2_build(K2Args a)
{
    const int blk  = blockIdx.x;
    const int j    = threadIdx.x;
    const int side = blk / 6;            // 0 = x-side, 1 = y-side
    const int t    = blk % 6;
    const int b    = t % 3;              // behavior: 0 buy, 1 cart, 2 pv

    const float* p; const float* W1; const float* c;
    if (side == 0) {
        if (t < 3) { p = &g_P[b * 64];           W1 = a.w1[4 * b + 0]; c = a.w[4 * b + 0]; } // uu
        else       { p = &g_P[384 + b * 64];     W1 = a.w1[4 * b + 1]; c = a.w[4 * b + 1]; } // ui
    } else {
        if (t < 3) { p = &g_P[384 + (3 + b) * 64]; W1 = a.w1[4 * b + 3]; c = a.w[4 * b + 3]; } // ii
        else       { p = &g_P[(3 + b) * 64];       W1 = a.w1[4 * b + 2]; c = a.w[4 * b + 2]; } // iu
    }
    const float coef = 0.25f * ((b == 0) ? 0.6f : (b == 1) ? 0.3f : 0.1f);

    float u0 = 0.f, u1 = 0.f, u2 = 0.f, u3 = 0.f;
#pragma unroll
    for (int k = 0; k < 64; k += 4) {
        u0 += p[k + 0] * W1[(k + 0) * 64 + j];
        u1 += p[k + 1] * W1[(k + 1) * 64 + j];
        u2 += p[k + 2] * W1[(k + 2) * 64 + j];
        u3 += p[k + 3] * W1[(k + 3) * 64 + j];
    }
    const float d = coef * ((u0 + u1) + (u2 + u3));
    if (side == 0) { g_dx[t * 64 + j] = d; g_cx[t * 64 + j] = c[j]; }
    else           { g_dy[t * 64 + j] = d; g_cy[t * 64 + j] = c[j]; }
}

// ---------------------------------------------------------------------------
// k3 fused: out[i] = 0.5 * x_i + sum_t (x_i . c_t) d_t
// 8 lanes per row; c and d both from shared each iteration (low regs).
// ---------------------------------------------------------------------------
__global__ __launch_bounds__(256, 4) void k3_apply(K3Args A)
{
    const int side = (blockIdx.x >= GX) ? 1 : 0;
    const int bid  = side ? (blockIdx.x - GX) : blockIdx.x;
    const int nb   = side ? GY : GX;
    const float* __restrict__ emb = side ? A.embY : A.embX;
    const int*   __restrict__ ids = side ? A.idsY : A.idsX;
    const int n = side ? A.nY : A.nX;
    float* __restrict__ out = side ? A.outY : A.outX;

    __shared__ float sc[384];
    __shared__ float sd[384];
    {
        const float* cv = side ? g_cy : g_cx;
        const float* dv = side ? g_dy : g_dx;
        for (int i = threadIdx.x; i < 384; i += 256) {
            sc[i] = cv[i];
            sd[i] = dv[i];
        }
    }
    __syncthreads();

    const int tid   = threadIdx.x;
    const int rslot = tid >> 3;       // 0..31
    const int col   = (tid & 7) * 8;

    for (int base = bid * 32; base < n; base += nb * 32) {
        const int r  = base + rslot;
        const int id = ids[r];
        const float4 u0 = *reinterpret_cast<const float4*>(emb + (size_t)id * D + col);
        const float4 u1 = *reinterpret_cast<const float4*>(emb + (size_t)id * D + col + 4);
        float x[8];
        x[0] = 0.1f * u0.x; x[1] = 0.1f * u0.y; x[2] = 0.1f * u0.z; x[3] = 0.1f * u0.w;
        x[4] = 0.1f * u1.x; x[5] = 0.1f * u1.y; x[6] = 0.1f * u1.z; x[7] = 0.1f * u1.w;

        float a[6];
#pragma unroll
        for (int t = 0; t < 6; t++) {
            const float4 c0 = *reinterpret_cast<const float4*>(&sc[t * 64 + col]);
            const float4 c1 = *reinterpret_cast<const float4*>(&sc[t * 64 + col + 4]);
            a[t] = x[0] * c0.x + x[1] * c0.y + x[2] * c0.z + x[3] * c0.w
                 + x[4] * c1.x + x[5] * c1.y + x[6] * c1.z + x[7] * c1.w;
        }
#pragma unroll
        for (int off = 4; off; off >>= 1)
#pragma unroll
            for (int t = 0; t < 6; t++)
                a[t] += __shfl_xor_sync(0xffffffffu, a[t], off);

        float o[8];
#pragma unroll
        for (int j = 0; j < 8; j++) o[j] = 0.5f * x[j];
#pragma unroll
        for (int t = 0; t < 6; t++) {
            const float4 d0 = *reinterpret_cast<const float4*>(&sd[t * 64 + col]);
            const float4 d1 = *reinterpret_cast<const float4*>(&sd[t * 64 + col + 4]);
            o[0] += a[t] * d0.x; o[1] += a[t] * d0.y;
            o[2] += a[t] * d0.z; o[3] += a[t] * d0.w;
            o[4] += a[t] * d1.x; o[5] += a[t] * d1.y;
            o[6] += a[t] * d1.z; o[7] += a[t] * d1.w;
        }

        float4 o0, o1;
        o0.x = o[0]; o0.y = o[1]; o0.z = o[2]; o0.w = o[3];
        o1.x = o[4]; o1.y = o[5]; o1.z = o[6]; o1.w = o[7];
        *reinterpret_cast<float4*>(out + (size_t)r * D + col)     = o0;
        *reinterpret_cast<float4*>(out + (size_t)r * D + col + 4) = o1;
    }
}

// ---------------------------------------------------------------------------
extern "C" void kernel_launch(void* const* d_in, const int* in_sizes, int n_in,
                              void* d_out, int out_size)
{
    const int*   uid = (const int*)d_in[0];
    const int*   iid = (const int*)d_in[1];
    const float* ue  = (const float*)d_in[2];
    const float* ie  = (const float*)d_in[3];
    const int nuser = in_sizes[0];
    const int nitem = in_sizes[1];

    // setup_inputs interleaves _w / _w1 per vec:
    //   d_in[4 + 2*v] = _VEC[v]_w,  d_in[5 + 2*v] = _VEC[v]_w1
    K2Args ka;
    for (int v = 0; v < 12; v++) {
        ka.w[v]  = (const float*)d_in[4 + 2 * v];
        ka.w1[v] = (const float*)d_in[5 + 2 * v];
    }

    K1Args k1a;
    k1a.embX = ue; k1a.idsX = uid; k1a.nX = nuser;
    k1a.embY = ie; k1a.idsY = iid; k1a.nY = nitem;
    for (int b = 0; b < 3; b++) {
        k1a.wX[b]     = ka.w[4 * b + 0]; // uu  -> Px slots 0..2
        k1a.wX[3 + b] = ka.w[4 * b + 2]; // iu  -> Px slots 3..5
        k1a.wY[b]     = ka.w[4 * b + 1]; // ui  -> Py slots 0..2
        k1a.wY[3 + b] = ka.w[4 * b + 3]; // ii  -> Py slots 3..5
    }

    float* out = (float*)d_out;
    float* edge_out = out + (size_t)(nuser + nitem) * D;

    K3Args k3a;
    k3a.embX = ue; k3a.idsX = uid; k3a.nX = nuser; k3a.outX = out;
    k3a.embY = ie; k3a.idsY = iid; k3a.nY = nitem; k3a.outY = out + (size_t)nuser * D;

    k0_zero<<<1, 768>>>();
    k_edge<<<1, 64>>>((const float*)d_in[28], (const float*)d_in[29],
                      (const float*)d_in[30], edge_out);
    k1_gramvec<<<GX + GY, 256>>>(k1a);
    k2_build<<<12, 64>>>(ka);
    k3_apply<<<GX + GY, 256>>>(k3a);
}

// round 6
// speedup vs baseline: 1.1546x; 1.0215x over previous
#include <cuda_runtime.h>
#include <cstdint>

#define D 64
#define GX 444            // X-side blocks (300K rows)
#define GY 740            // Y-side blocks (500K rows); 444+740 = 1184

// Global accumulators / tables (no allocation allowed)
__device__ float g_P[768];                 // [0:384) = Px_stored (6x64), [384:768) = Py_stored
__device__ float g_cx[384], g_dx[384];
__device__ float g_cy[384], g_dy[384];

struct K1Args {
    const float* embX; const int* idsX; int nX;
    const float* embY; const int* idsY; int nY;
    const float* wX[6];   // uu(buy,cart,pv), iu(buy,cart,pv)
    const float* wY[6];   // ui(buy,cart,pv), ii(buy,cart,pv)
};
struct K2Args {
    const float* w[12];    // logical: buy_uu, buy_ui, buy_iu, buy_ii, cart_*, pv_*
    const float* w1[12];
    const float* edges[3];
};
struct K3Args {
    const float* embX; const int* idsX; int nX; float* outX;
    const float* embY; const int* idsY; int nY; float* outY;
};

// packed fp32 FMA (Blackwell f32x2 pipe; ptxas won't auto-fuse)
__device__ __forceinline__ float2 ffma2(float2 a, float2 b, float2 c) {
    float2 d;
    asm("{\n\t"
        ".reg .b64 Ar,Br,Cr,Dr;\n\t"
        "mov.b64 Ar,{%2,%3};\n\t"
        "mov.b64 Br,{%4,%5};\n\t"
        "mov.b64 Cr,{%6,%7};\n\t"
        "fma.rn.f32x2 Dr,Ar,Br,Cr;\n\t"
        "mov.b64 {%0,%1},Dr;\n\t"
        "}" : "=f"(d.x), "=f"(d.y)
            : "f"(a.x), "f"(a.y), "f"(b.x), "f"(b.y), "f"(c.x), "f"(c.y));
    return d;
}
__device__ __forceinline__ float2 fmul2(float2 a, float2 b) {
    return ffma2(a, b, make_float2(0.f, 0.f));
}

// ---------------------------------------------------------------------------
__global__ void k0_zero() { g_P[threadIdx.x] = 0.0f; }

// ---------------------------------------------------------------------------
// k1 fused: p_t(stored) = src^T (src (0.1*w_t)), 6 vectors per side.
// Warp pair shares 4 rows; even warp t=0..2, odd warp t=3..5.
// 8 lanes per row; packed f32x2 math.
// ---------------------------------------------------------------------------
__global__ __launch_bounds__(256, 4) void k1_gramvec(K1Args A)
{
    const int side = (blockIdx.x >= GX) ? 1 : 0;
    const int bid  = side ? (blockIdx.x - GX) : blockIdx.x;
    const int nb   = side ? GY : GX;
    const float* __restrict__ emb = side ? A.embY : A.embX;
    const int*   __restrict__ ids = side ? A.idsY : A.idsX;
    const int n = side ? A.nY : A.nX;

    __shared__ float sw[384];     // 0.1 * weights
    __shared__ float sp[384];
    const int tid = threadIdx.x;
    {
        const float* const* Wp = side ? A.wY : A.wX;
        for (int i = tid; i < 384; i += 256) {
            sw[i] = 0.1f * Wp[i >> 6][i & 63];
            sp[i] = 0.0f;
        }
    }
    __syncthreads();

    const int wid  = tid >> 5;
    const int lane = tid & 31;
    const int tg   = (wid & 1) * 3;                    // t-group offset
    const int rsl  = (wid >> 1) * 4 + (lane >> 3);     // row slot 0..15
    const int col  = (lane & 7) * 8;

    float2 acc[3][4];
#pragma unroll
    for (int t = 0; t < 3; t++)
#pragma unroll
        for (int j = 0; j < 4; j++) acc[t][j] = make_float2(0.f, 0.f);

    for (int base = bid * 16; base < n; base += nb * 16) {
        const int id = ids[base + rsl];
        const float4 u0 = *reinterpret_cast<const float4*>(emb + (size_t)id * D + col);
        const float4 u1 = *reinterpret_cast<const float4*>(emb + (size_t)id * D + col + 4);
        float2 x2[4];
        x2[0] = make_float2(u0.x, u0.y); x2[1] = make_float2(u0.z, u0.w);
        x2[2] = make_float2(u1.x, u1.y); x2[3] = make_float2(u1.z, u1.w);

        float a[3];
#pragma unroll
        for (int t = 0; t < 3; t++) {
            const float4 w0 = *reinterpret_cast<const float4*>(&sw[(tg + t) * 64 + col]);
            const float4 w1 = *reinterpret_cast<const float4*>(&sw[(tg + t) * 64 + col + 4]);
            float2 s = fmul2(x2[0], make_float2(w0.x, w0.y));
            s = ffma2(x2[1], make_float2(w0.z, w0.w), s);
            s = ffma2(x2[2], make_float2(w1.x, w1.y), s);
            s = ffma2(x2[3], make_float2(w1.z, w1.w), s);
            a[t] = s.x + s.y;
        }
#pragma unroll
        for (int off = 4; off; off >>= 1)
#pragma unroll
            for (int t = 0; t < 3; t++)
                a[t] += __shfl_xor_sync(0xffffffffu, a[t], off);
#pragma unroll
        for (int t = 0; t < 3; t++) {
            const float2 av = make_float2(a[t], a[t]);
#pragma unroll
            for (int j = 0; j < 4; j++)
                acc[t][j] = ffma2(av, x2[j], acc[t][j]);
        }
    }

    // fold the 4 row-slot groups per warp
#pragma unroll
    for (int off = 8; off <= 16; off <<= 1)
#pragma unroll
        for (int t = 0; t < 3; t++)
#pragma unroll
            for (int j = 0; j < 4; j++) {
                acc[t][j].x += __shfl_xor_sync(0xffffffffu, acc[t][j].x, off);
                acc[t][j].y += __shfl_xor_sync(0xffffffffu, acc[t][j].y, off);
            }

    if (lane < 8) {
#pragma unroll
        for (int t = 0; t < 3; t++)
#pragma unroll
            for (int j = 0; j < 4; j++) {
                atomicAdd(&sp[(tg + t) * 64 + col + 2 * j],     acc[t][j].x);
                atomicAdd(&sp[(tg + t) * 64 + col + 2 * j + 1], acc[t][j].y);
            }
    }
    __syncthreads();

    float* gp = g_P + side * 384;
    for (int i = tid; i < 384; i += 256)
        atomicAdd(&gp[i], sp[i]);
}

// ---------------------------------------------------------------------------
// k2: build c/d tables. Blocks 0..11: one (side,term). Block 12: edge copy.
// p_true = 0.1 * p_stored  (0.1 folded into k1's weights once) -> coef *= 0.1
// ---------------------------------------------------------------------------
__global__ __launch_bounds__(64) void k2_build(K2Args a, float* __restrict__ edge_out)
{
    const int blk = blockIdx.x;
    const int j   = threadIdx.x;

    if (blk == 12) {
#pragma unroll
        for (int e = 0; e < 3; e++)
            edge_out[e * 64 + j] = a.edges[e][j];
        return;
    }

    const int side = blk / 6;
    const int t    = blk % 6;
    const int b    = t % 3;              // 0 buy, 1 cart, 2 pv

    const float* p; const float* W1; const float* c;
    if (side == 0) {
        if (t < 3) { p = &g_P[b * 64];           W1 = a.w1[4 * b + 0]; c = a.w[4 * b + 0]; } // uu
        else       { p = &g_P[384 + b * 64];     W1 = a.w1[4 * b + 1]; c = a.w[4 * b + 1]; } // ui
    } else {
        if (t < 3) { p = &g_P[384 + (3 + b) * 64]; W1 = a.w1[4 * b + 3]; c = a.w[4 * b + 3]; } // ii
        else       { p = &g_P[(3 + b) * 64];       W1 = a.w1[4 * b + 2]; c = a.w[4 * b + 2]; } // iu
    }
    const float coef = 0.025f * ((b == 0) ? 0.6f : (b == 1) ? 0.3f : 0.1f);

    float u0 = 0.f, u1 = 0.f, u2 = 0.f, u3 = 0.f;
#pragma unroll
    for (int k = 0; k < 64; k += 4) {
        u0 += p[k + 0] * W1[(k + 0) * 64 + j];
        u1 += p[k + 1] * W1[(k + 1) * 64 + j];
        u2 += p[k + 2] * W1[(k + 2) * 64 + j];
        u3 += p[k + 3] * W1[(k + 3) * 64 + j];
    }
    const float d = coef * ((u0 + u1) + (u2 + u3));
    if (side == 0) { g_dx[t * 64 + j] = d; g_cx[t * 64 + j] = c[j]; }
    else           { g_dy[t * 64 + j] = d; g_cy[t * 64 + j] = c[j]; }
}

// ---------------------------------------------------------------------------
// k3 fused: out[i] = 0.05 * x_raw + sum_t (x_raw . (0.1 c_t)) d_t
// 8 lanes per row; packed f32x2 math; c,d from shared.
// ---------------------------------------------------------------------------
__global__ __launch_bounds__(256, 4) void k3_apply(K3Args A)
{
    const int side = (blockIdx.x >= GX) ? 1 : 0;
    const int bid  = side ? (blockIdx.x - GX) : blockIdx.x;
    const int nb   = side ? GY : GX;
    const float* __restrict__ emb = side ? A.embY : A.embX;
    const int*   __restrict__ ids = side ? A.idsY : A.idsX;
    const int n = side ? A.nY : A.nX;
    float* __restrict__ out = side ? A.outY : A.outX;

    __shared__ float sc[384];   // 0.1 * c
    __shared__ float sd[384];
    {
        const float* cv = side ? g_cy : g_cx;
        const float* dv = side ? g_dy : g_dx;
        for (int i = threadIdx.x; i < 384; i += 256) {
            sc[i] = 0.1f * cv[i];
            sd[i] = dv[i];
        }
    }
    __syncthreads();

    const int tid   = threadIdx.x;
    const int rslot = tid >> 3;
    const int col   = (tid & 7) * 8;
    const float2 h05 = make_float2(0.05f, 0.05f);

    for (int base = bid * 32; base < n; base += nb * 32) {
        const int r  = base + rslot;
        const int id = ids[r];
        const float4 u0 = *reinterpret_cast<const float4*>(emb + (size_t)id * D + col);
        const float4 u1 = *reinterpret_cast<const float4*>(emb + (size_t)id * D + col + 4);
        float2 x2[4];
        x2[0] = make_float2(u0.x, u0.y); x2[1] = make_float2(u0.z, u0.w);
        x2[2] = make_float2(u1.x, u1.y); x2[3] = make_float2(u1.z, u1.w);

        float a[6];
#pragma unroll
        for (int t = 0; t < 6; t++) {
            const float4 c0 = *reinterpret_cast<const float4*>(&sc[t * 64 + col]);
            const float4 c1 = *reinterpret_cast<const float4*>(&sc[t * 64 + col + 4]);
            float2 s = fmul2(x2[0], make_float2(c0.x, c0.y));
            s = ffma2(x2[1], make_float2(c0.z, c0.w), s);
            s = ffma2(x2[2], make_float2(c1.x, c1.y), s);
            s = ffma2(x2[3], make_float2(c1.z, c1.w), s);
            a[t] = s.x + s.y;
        }
#pragma unroll
        for (int off = 4; off; off >>= 1)
#pragma unroll
            for (int t = 0; t < 6; t++)
                a[t] += __shfl_xor_sync(0xffffffffu, a[t], off);

        float2 o2[4];
#pragma unroll
        for (int j = 0; j < 4; j++) o2[j] = fmul2(x2[j], h05);
#pragma unroll
        for (int t = 0; t < 6; t++) {
            const float4 d0 = *reinterpret_cast<const float4*>(&sd[t * 64 + col]);
            const float4 d1 = *reinterpret_cast<const float4*>(&sd[t * 64 + col + 4]);
            const float2 av = make_float2(a[t], a[t]);
            o2[0] = ffma2(av, make_float2(d0.x, d0.y), o2[0]);
            o2[1] = ffma2(av, make_float2(d0.z, d0.w), o2[1]);
            o2[2] = ffma2(av, make_float2(d1.x, d1.y), o2[2]);
            o2[3] = ffma2(av, make_float2(d1.z, d1.w), o2[3]);
        }

        float4 w0, w1;
        w0.x = o2[0].x; w0.y = o2[0].y; w0.z = o2[1].x; w0.w = o2[1].y;
        w1.x = o2[2].x; w1.y = o2[2].y; w1.z = o2[3].x; w1.w = o2[3].y;
        *reinterpret_cast<float4*>(out + (size_t)r * D + col)     = w0;
        *reinterpret_cast<float4*>(out + (size_t)r * D + col + 4) = w1;
    }
}

// ---------------------------------------------------------------------------
extern "C" void kernel_launch(void* const* d_in, const int* in_sizes, int n_in,
                              void* d_out, int out_size)
{
    const int*   uid = (const int*)d_in[0];
    const int*   iid = (const int*)d_in[1];
    const float* ue  = (const float*)d_in[2];
    const float* ie  = (const float*)d_in[3];
    const int nuser = in_sizes[0];
    const int nitem = in_sizes[1];

    K2Args ka;
    for (int v = 0; v < 12; v++) {
        ka.w[v]  = (const float*)d_in[4 + 2 * v];
        ka.w1[v] = (const float*)d_in[5 + 2 * v];
    }
    ka.edges[0] = (const float*)d_in[28];
    ka.edges[1] = (const float*)d_in[29];
    ka.edges[2] = (const float*)d_in[30];

    K1Args k1a;
    k1a.embX = ue; k1a.idsX = uid; k1a.nX = nuser;
    k1a.embY = ie; k1a.idsY = iid; k1a.nY = nitem;
    for (int b = 0; b < 3; b++) {
        k1a.wX[b]     = ka.w[4 * b + 0]; // uu
        k1a.wX[3 + b] = ka.w[4 * b + 2]; // iu
        k1a.wY[b]     = ka.w[4 * b + 1]; // ui
        k1a.wY[3 + b] = ka.w[4 * b + 3]; // ii
    }

    float* out = (float*)d_out;
    float* edge_out = out + (size_t)(nuser + nitem) * D;

    K3Args k3a;
    k3a.embX = ue; k3a.idsX = uid; k3a.nX = nuser; k3a.outX = out;
    k3a.embY = ie; k3a.idsY = iid; k3a.nY = nitem; k3a.outY = out + (size_t)nuser * D;

    // 4 launches; ncu captures launch #4 = k3_apply.
    k0_zero<<<1, 768>>>();
    k1_gramvec<<<GX + GY, 256>>>(k1a);
    k2_build<<<13, 64>>>(ka, edge_out);
    k3_apply<<<GX + GY, 256>>>(k3a);
}